// round 14
// baseline (speedup 1.0000x reference)
#include <cuda_runtime.h>
#include <cuda_fp16.h>
#include <math.h>
#include <stdint.h>

// ---------------- problem constants ----------------
#define TT     16384            // tokens = B*S
#define DD     1024             // n_embd
#define EE     8                // experts
#define DFF    2048             // per-expert ffn width
#define NN     32768            // N = T*K
#define RBLOCKS 512
#define MAX_TILES 264
#define MAX_ROWS (MAX_TILES*128)
#define OUT_OFF ((size_t)TT*DD)
#define G1_BLOCKS (16*MAX_TILES)   // 4224
#define G2_BLOCKS (8*MAX_TILES)    // 2112
#define CONV1_BLOCKS 16384          // (EE*DFF/32) * (DD/32)
#define CONV2_BLOCKS 16384          // (DD/32) * (DFF/32) * EE

#define STAGES 4
#define STAGE_BYTES 16384       // A 8K | B 8K (128 rows x 64B each)
#define SMEM_BYTES (STAGES*STAGE_BYTES)

// ---------------- device scratch (~228 MiB) ----------------
__device__ int   g_counts[EE];
__device__ int   g_cursor[EE];
__device__ int   g_offpad[EE];
__device__ int   g_tile_expert[MAX_TILES];
__device__ int   g_done[MAX_TILES];
__device__ int   g_sel[NN];
__device__ float g_rw[NN];
__device__ int   g_list[MAX_ROWS];
__device__ float g_partials[RBLOCKS][17];   // z | p[8] | cnt[8]

__device__ __half g_zeroh[DD];                        // stays zero (never written)
__device__ __half g_xh[(size_t)TT*DD];                // 32 MiB (written by router)
__device__ __half g_w1t[(size_t)EE*DFF*DD];           // 32 MiB  [e*DFF+f][d]
__device__ __half g_w2t[(size_t)EE*DD*DFF];           // 32 MiB  [e*DD+d][f]
__device__ __half g_H[(size_t)MAX_ROWS*DFF];          // 132 MiB post-gelu hidden fp16

// ---------------- asm helpers (baseline sm_80+ ISA only) ----------------
__device__ __forceinline__ uint32_t smem_u32(const void* p) {
    uint32_t r;
    asm("{ .reg .u64 t; cvta.to.shared.u64 t, %1; cvt.u32.u64 %0, t; }" : "=r"(r) : "l"(p));
    return r;
}
__device__ __forceinline__ void cp16(uint32_t dst, const void* src) {
    asm volatile("cp.async.cg.shared.global [%0], [%1], 16;" :: "r"(dst), "l"(src) : "memory");
}
#define CP_COMMIT() asm volatile("cp.async.commit_group;" ::: "memory")
#define CP_WAIT0()  asm volatile("cp.async.wait_group 0;" ::: "memory")
#define CP_WAIT1()  asm volatile("cp.async.wait_group 1;" ::: "memory")
#define CP_WAIT2()  asm volatile("cp.async.wait_group 2;" ::: "memory")
#define CP_WAIT3()  asm volatile("cp.async.wait_group 3;" ::: "memory")

__device__ __forceinline__ void ldsm4(uint32_t* r, uint32_t addr) {
    asm volatile("ldmatrix.sync.aligned.m8n8.x4.shared.b16 {%0,%1,%2,%3}, [%4];"
        : "=r"(r[0]), "=r"(r[1]), "=r"(r[2]), "=r"(r[3]) : "r"(addr));
}
__device__ __forceinline__ void mma16816(float* d, const uint32_t* a, const uint32_t* b) {
    asm volatile(
        "mma.sync.aligned.m16n8k16.row.col.f32.f16.f16.f32 "
        "{%0,%1,%2,%3}, {%4,%5,%6,%7}, {%8,%9}, {%0,%1,%2,%3};"
        : "+f"(d[0]), "+f"(d[1]), "+f"(d[2]), "+f"(d[3])
        : "r"(a[0]), "r"(a[1]), "r"(a[2]), "r"(a[3]), "r"(b[0]), "r"(b[1]));
}
// swizzled byte offset inside one 128x32-fp16 smem tile (row stride 64B)
__device__ __forceinline__ uint32_t swz(int row, int c) {
    return (uint32_t)(row * 64 + ((c ^ ((row >> 1) & 3)) * 16));
}

// ================= PREP: router (bids 0..511) | conv_w1 | conv_w2, one launch =======
__global__ __launch_bounds__(256) void prep_kernel(
    const float* __restrict__ x, const float* __restrict__ router_w,
    const float* __restrict__ w1, const float* __restrict__ w2,
    float* __restrict__ d_out)
{
    __shared__ float rw_s[EE * DD];       // router weights (32 KB)
    __shared__ float warp_part[8][17];
    __shared__ float t[32][33];           // conv transpose tile

    int bid = blockIdx.x;
    int tid = threadIdx.x;

    if (bid < RBLOCKS) {
        // ---------------- router + d_out zeroing + fused x->fp16 ----------------
        // zero this block's chunk of d_out (TT*DD/4 float4s over 512 blocks)
        {
            float4* o4 = (float4*)d_out;
            int per = TT * DD / 4 / RBLOCKS;        // 8192 float4 per block
            int base = bid * per;
            for (int i = tid; i < per; i += 256)
                o4[base + i] = make_float4(0.f, 0.f, 0.f, 0.f);
        }
        for (int i = tid; i < EE * DD; i += 256) rw_s[i] = router_w[i];
        __syncthreads();

        int warp = tid >> 5, lane = tid & 31;
        int wg = bid * 8 + warp;
        float zp = 0.f;
        float pp[EE], cnt[EE];
        #pragma unroll
        for (int e = 0; e < EE; e++) { pp[e] = 0.f; cnt[e] = 0.f; }

        for (int tk = wg; tk < TT; tk += RBLOCKS * 8) {
            const float* xr = x + (size_t)tk * DD;
            float xv[32];
            #pragma unroll
            for (int i = 0; i < 32; i++) xv[i] = xr[lane + 32 * i];
            __half* xo = g_xh + (size_t)tk * DD + lane;
            #pragma unroll
            for (int i = 0; i < 32; i++) xo[32 * i] = __float2half_rn(xv[i]);

            float logit[EE];
            #pragma unroll
            for (int e = 0; e < EE; e++) {
                float s = 0.f;
                #pragma unroll
                for (int i = 0; i < 32; i++) s = fmaf(xv[i], rw_s[e * DD + lane + 32 * i], s);
                #pragma unroll
                for (int o = 16; o > 0; o >>= 1) s += __shfl_xor_sync(0xFFFFFFFFu, s, o);
                logit[e] = s;
            }
            if (lane == 0) {
                float m = logit[0];
                #pragma unroll
                for (int e = 1; e < EE; e++) m = fmaxf(m, logit[e]);
                float se = 0.f, p[EE];
                #pragma unroll
                for (int e = 0; e < EE; e++) { p[e] = expf(logit[e] - m); se += p[e]; }
                float inv = 1.f / se;
                float lse = m + logf(se);
                zp += lse * lse;
                int i1 = -1, i2 = -1; float p1 = -1.f, p2 = -1.f;
                #pragma unroll
                for (int e = 0; e < EE; e++) {
                    float pe = p[e] * inv;
                    pp[e] += pe;
                    if (pe > p1)      { p2 = p1; i2 = i1; p1 = pe; i1 = e; }
                    else if (pe > p2) { p2 = pe; i2 = e; }
                }
                float s12 = p1 + p2;
                g_sel[2 * tk] = i1;  g_sel[2 * tk + 1] = i2;
                g_rw[2 * tk] = p1 / s12;  g_rw[2 * tk + 1] = p2 / s12;
                cnt[i1] += 1.f;
                cnt[i2] += 1.f;
            }
        }
        if (lane == 0) {
            warp_part[warp][0] = zp;
            #pragma unroll
            for (int e = 0; e < EE; e++) {
                warp_part[warp][e + 1] = pp[e];
                warp_part[warp][e + 9] = cnt[e];
            }
        }
        __syncthreads();
        if (tid == 0) {
            float acc[17];
            #pragma unroll
            for (int j = 0; j < 17; j++) acc[j] = 0.f;
            for (int w = 0; w < 8; w++)
                for (int j = 0; j < 17; j++) acc[j] += warp_part[w][j];
            for (int j = 0; j < 17; j++) g_partials[bid][j] = acc[j];
        }
    } else if (bid < RBLOCKS + CONV1_BLOCKS) {
        // ---------------- conv_w1: [D][E*DFF] -> [E*DFF][D] fp16 ----------------
        int idx = bid - RBLOCKS;
        int c0 = (idx & 511) * 32, d0 = (idx >> 9) * 32;
        int tx = tid & 31, ty = tid >> 5;
        #pragma unroll
        for (int j = 0; j < 32; j += 8)
            t[ty + j][tx] = w1[(size_t)(d0 + ty + j) * (EE * DFF) + c0 + tx];
        __syncthreads();
        #pragma unroll
        for (int j = 0; j < 32; j += 8)
            g_w1t[(size_t)(c0 + ty + j) * DD + d0 + tx] = __float2half_rn(t[tx][ty + j]);
    } else {
        // ---------------- conv_w2: [E*DFF][D] -> [e][d][f] fp16 ----------------
        int idx = bid - RBLOCKS - CONV1_BLOCKS;
        int d0 = (idx & 31) * 32, f0 = ((idx >> 5) & 63) * 32, e = idx >> 11;
        int tx = tid & 31, ty = tid >> 5;
        #pragma unroll
        for (int j = 0; j < 32; j += 8)
            t[ty + j][tx] = w2[(size_t)(e * DFF + f0 + ty + j) * DD + d0 + tx];
        __syncthreads();
        #pragma unroll
        for (int j = 0; j < 32; j += 8)
            g_w2t[(size_t)(e * DD + d0 + ty + j) * DFF + f0 + tx] = __float2half_rn(t[tx][ty + j]);
    }
}

// ---------------- finalize: reduce partials, losses, offsets, pads, g_done ----------
__global__ __launch_bounds__(256) void moe_finalize_kernel(float* __restrict__ d_out) {
    __shared__ float wsum[8][17];
    __shared__ int s_off[EE], s_cnt[EE], s_blk[EE];
    int tid = threadIdx.x, lane = tid & 31, warp = tid >> 5;
    float acc[17];
    #pragma unroll
    for (int j = 0; j < 17; j++) acc[j] = 0.f;
    for (int b = tid; b < RBLOCKS; b += 256)
        #pragma unroll
        for (int j = 0; j < 17; j++) acc[j] += g_partials[b][j];
    #pragma unroll
    for (int j = 0; j < 17; j++)
        #pragma unroll
        for (int o = 16; o > 0; o >>= 1) acc[j] += __shfl_xor_sync(0xFFFFFFFFu, acc[j], o);
    if (lane == 0)
        #pragma unroll
        for (int j = 0; j < 17; j++) wsum[warp][j] = acc[j];
    __syncthreads();

    if (tid == 0) {
        float tot[17];
        #pragma unroll
        for (int j = 0; j < 17; j++) {
            float s = 0.f;
            for (int w = 0; w < 8; w++) s += wsum[w][j];
            tot[j] = s;
        }
        float zl = tot[0] / (float)TT;
        float lb = 0.f, fi[EE];
        int cnts[EE];
        for (int e = 0; e < EE; e++) {
            cnts[e] = (int)lrintf(tot[e + 9]);
            fi[e] = (float)cnts[e] / (float)NN;
            lb += fi[e] * (tot[e + 1] / (float)TT);
        }
        lb *= (float)EE;
        d_out[OUT_OFF + 0] = zl;
        d_out[OUT_OFF + 1] = lb;
        for (int e = 0; e < EE; e++) d_out[OUT_OFF + 2 + e] = fi[e];

        int off = 0;
        for (int e = 0; e < EE; e++) {
            g_counts[e] = cnts[e];
            g_offpad[e] = off;
            g_cursor[e] = 0;
            int blocks = (cnts[e] + 127) >> 7;
            s_off[e] = off; s_cnt[e] = cnts[e]; s_blk[e] = blocks;
            off += blocks << 7;
        }
        int ti = 0;
        for (int e = 0; e < EE; e++)
            for (int b = 0; b < s_blk[e]; b++) g_tile_expert[ti++] = e;
        for (; ti < MAX_TILES; ti++) g_tile_expert[ti] = -1;
    }
    __syncthreads();
    // zero g_done + fill pad slots of g_list with -1 (parallel; <= 1016 pads)
    for (int i = tid; i < MAX_TILES; i += 256) g_done[i] = 0;
    for (int e = 0; e < EE; e++) {
        int start = s_off[e] + s_cnt[e];
        int end   = s_off[e] + (s_blk[e] << 7);
        for (int i = start + tid; i < end; i += 256) g_list[i] = -1;
    }
}

__global__ void moe_scatter_kernel() {
    int n = blockIdx.x * 256 + threadIdx.x;
    if (n >= NN) return;
    int e = g_sel[n];
    int pos = atomicAdd(&g_cursor[e], 1);
    g_list[g_offpad[e] + pos] = n;
}

// ================= FUSED FFN: GEMM1 blocks [0, G1_BLOCKS), GEMM2 after ==============
__global__ __launch_bounds__(256, 2) void moe_ffn_kernel(float* __restrict__ d_out) {
    extern __shared__ char sm[];
    __shared__ int   s_tok[128];
    __shared__ float s_rw[128];

    int bid = blockIdx.x;
    int tid = threadIdx.x;
    uint32_t sb = smem_u32(sm);
    int lane = tid & 31, w = tid >> 5;
    int wm = w >> 1, wn = w & 1;

    int rA[2], swA[2];
    #pragma unroll
    for (int mf = 0; mf < 2; mf++) {
        rA[mf] = wm * 32 + mf * 16 + (lane & 15);
        swA[mf] = (rA[mf] >> 1) & 3;
    }
    int kcA = lane >> 4;
    int rB[4], swB[4];
    #pragma unroll
    for (int np = 0; np < 4; np++) {
        rB[np] = wn * 64 + np * 16 + (lane & 7) + ((lane >> 4) << 3);
        swB[np] = (rB[np] >> 1) & 3;
    }
    int kcB = (lane >> 3) & 1;

    float acc[2][8][4];
    #pragma unroll
    for (int mf = 0; mf < 2; mf++)
        #pragma unroll
        for (int nf = 0; nf < 8; nf++)
            #pragma unroll
            for (int q = 0; q < 4; q++) acc[mf][nf][q] = 0.f;

    int arow = tid >> 1;
    int ac0 = (tid & 1) * 2;
    uint32_t d0 = swz(arow, ac0), d1 = swz(arow, ac0 + 1);
    int src0 = ac0 * 8, src1 = ac0 * 8 + 8;

    if (bid < G1_BLOCKS) {
        int bx = bid & 15, by = bid >> 4;
        int e = g_tile_expert[by];
        if (e < 0) return;

        if (tid < 128) {
            int n = g_list[by * 128 + tid];
            s_tok[tid] = (n >= 0) ? (n >> 1) : -1;
        }
        __syncthreads();

        int tok = s_tok[arow];
        const __half* Ah = (tok >= 0) ? g_xh + (size_t)tok * DD : g_zeroh;
        const __half* Bh = g_w1t + (size_t)(e * DFF + bx * 128 + arow) * DD;

        const int S = DD / 32;   // 32 slabs
        #define G1_LOAD(s) do {                                             \
            uint32_t base = sb + ((s) % STAGES) * STAGE_BYTES;              \
            int k0 = (s) * 32;                                              \
            cp16(base +    0 + d0, Ah + k0 + src0);                         \
            cp16(base +    0 + d1, Ah + k0 + src1);                         \
            cp16(base + 8192 + d0, Bh + k0 + src0);                         \
            cp16(base + 8192 + d1, Bh + k0 + src1);                         \
            CP_COMMIT();                                                    \
        } while (0)

        G1_LOAD(0); G1_LOAD(1); G1_LOAD(2);
        for (int s = 0; s < S; ++s) {
            if (s + 3 < S) { G1_LOAD(s + 3); CP_WAIT3(); }
            else if (s + 2 < S) { CP_WAIT2(); }
            else if (s + 1 < S) { CP_WAIT1(); }
            else { CP_WAIT0(); }
            __syncthreads();
            uint32_t base = sb + (s % STAGES) * STAGE_BYTES;
            #pragma unroll
            for (int kk = 0; kk < 2; ++kk) {
                uint32_t ah[2][4], bfr[4][4];
                #pragma unroll
                for (int mf = 0; mf < 2; mf++) {
                    uint32_t ao = (uint32_t)(rA[mf] * 64 + (((kk * 2 + kcA) ^ swA[mf]) * 16));
                    ldsm4(ah[mf], base + ao);
                }
                #pragma unroll
                for (int np = 0; np < 4; np++) {
                    uint32_t bo = (uint32_t)(rB[np] * 64 + (((kk * 2 + kcB) ^ swB[np]) * 16));
                    ldsm4(bfr[np], base + 8192 + bo);
                }
                #pragma unroll
                for (int mf = 0; mf < 2; mf++)
                    #pragma unroll
                    for (int np = 0; np < 4; np++) {
                        mma16816(acc[mf][np*2],   ah[mf], &bfr[np][0]);
                        mma16816(acc[mf][np*2+1], ah[mf], &bfr[np][2]);
                    }
            }
            __syncthreads();
        }
        #undef G1_LOAD

        #pragma unroll
        for (int mf = 0; mf < 2; mf++) {
            int r0 = wm * 32 + mf * 16 + (lane >> 2);
            #pragma unroll
            for (int nf = 0; nf < 8; nf++) {
                int c = wn * 64 + nf * 8 + (lane & 3) * 2;
                size_t base0 = (size_t)(by * 128 + r0) * DFF + bx * 128 + c;
                size_t base1 = (size_t)(by * 128 + r0 + 8) * DFF + bx * 128 + c;
                #pragma unroll
                for (int half_ = 0; half_ < 2; half_++) {
                    float v0 = acc[mf][nf][half_ * 2], v1 = acc[mf][nf][half_ * 2 + 1];
                    float gl0 = 0.5f * v0 * (1.f + erff(v0 * 0.70710678118654752f));
                    float gl1 = 0.5f * v1 * (1.f + erff(v1 * 0.70710678118654752f));
                    *(__half2*)(g_H + (half_ ? base1 : base0)) = __floats2half2_rn(gl0, gl1);
                }
            }
        }
        __threadfence();
        __syncthreads();
        if (tid == 0) atomicAdd(&g_done[by], 1);
    } else {
        int n2 = bid - G1_BLOCKS;
        int bx = n2 & 7, by = n2 >> 3;
        int e = g_tile_expert[by];
        if (e < 0) return;

        if (tid < 128) {
            int n = g_list[by * 128 + tid];
            s_tok[tid] = n;
            s_rw[tid] = (n >= 0) ? g_rw[n] : 0.f;
        }
        if (tid == 0) {
            int v;
            do {
                asm volatile("ld.global.acquire.gpu.b32 %0, [%1];"
                             : "=r"(v) : "l"(&g_done[by]) : "memory");
            } while (v < 16);
        }
        __syncthreads();

        const __half* Ah = g_H + (size_t)(by * 128 + arow) * DFF;
        const __half* Bh = g_w2t + (size_t)(e * DD + bx * 128 + arow) * DFF;

        const int S = DFF / 32;   // 64 slabs
        #define G2_LOAD(s) do {                                             \
            uint32_t base = sb + ((s) % STAGES) * STAGE_BYTES;              \
            int k0 = (s) * 32;                                              \
            cp16(base +    0 + d0, Ah + k0 + src0);                         \
            cp16(base +    0 + d1, Ah + k0 + src1);                         \
            cp16(base + 8192 + d0, Bh + k0 + src0);                         \
            cp16(base + 8192 + d1, Bh + k0 + src1);                         \
            CP_COMMIT();                                                    \
        } while (0)

        G2_LOAD(0); G2_LOAD(1); G2_LOAD(2);
        for (int s = 0; s < S; ++s) {
            if (s + 3 < S) { G2_LOAD(s + 3); CP_WAIT3(); }
            else if (s + 2 < S) { CP_WAIT2(); }
            else if (s + 1 < S) { CP_WAIT1(); }
            else { CP_WAIT0(); }
            __syncthreads();
            uint32_t base = sb + (s % STAGES) * STAGE_BYTES;
            #pragma unroll
            for (int kk = 0; kk < 2; ++kk) {
                uint32_t ah[2][4], bfr[4][4];
                #pragma unroll
                for (int mf = 0; mf < 2; mf++) {
                    uint32_t ao = (uint32_t)(rA[mf] * 64 + (((kk * 2 + kcA) ^ swA[mf]) * 16));
                    ldsm4(ah[mf], base + ao);
                }
                #pragma unroll
                for (int np = 0; np < 4; np++) {
                    uint32_t bo = (uint32_t)(rB[np] * 64 + (((kk * 2 + kcB) ^ swB[np]) * 16));
                    ldsm4(bfr[np], base + 8192 + bo);
                }
                #pragma unroll
                for (int mf = 0; mf < 2; mf++)
                    #pragma unroll
                    for (int np = 0; np < 4; np++) {
                        mma16816(acc[mf][np*2],   ah[mf], &bfr[np][0]);
                        mma16816(acc[mf][np*2+1], ah[mf], &bfr[np][2]);
                    }
            }
            __syncthreads();
        }
        #undef G2_LOAD

        #pragma unroll
        for (int mf = 0; mf < 2; mf++) {
            int r0 = wm * 32 + mf * 16 + (lane >> 2);
            int n0 = s_tok[r0], n1 = s_tok[r0 + 8];
            float w0 = s_rw[r0], w1v = s_rw[r0 + 8];
            #pragma unroll
            for (int nf = 0; nf < 8; nf++) {
                int c = bx * 128 + wn * 64 + nf * 8 + (lane & 3) * 2;
                if (n0 >= 0) {
                    float* p = d_out + (size_t)(n0 >> 1) * DD + c;
                    atomicAdd(p,     acc[mf][nf][0] * w0);
                    atomicAdd(p + 1, acc[mf][nf][1] * w0);
                }
                if (n1 >= 0) {
                    float* p = d_out + (size_t)(n1 >> 1) * DD + c;
                    atomicAdd(p,     acc[mf][nf][2] * w1v);
                    atomicAdd(p + 1, acc[mf][nf][3] * w1v);
                }
            }
        }
    }
}

// ---------------- launch ----------------
extern "C" void kernel_launch(void* const* d_in, const int* in_sizes, int n_in,
                              void* d_out, int out_size) {
    const float* x        = (const float*)d_in[0];
    const float* w1       = (const float*)d_in[1];
    const float* w2       = (const float*)d_in[2];
    const float* router_w = (const float*)d_in[3];
    float* out = (float*)d_out;

    cudaFuncSetAttribute(moe_ffn_kernel, cudaFuncAttributeMaxDynamicSharedMemorySize, SMEM_BYTES);

    prep_kernel<<<RBLOCKS + CONV1_BLOCKS + CONV2_BLOCKS, 256>>>(x, router_w, w1, w2, out);
    moe_finalize_kernel<<<1, 256>>>(out);
    moe_scatter_kernel<<<(NN + 255) / 256, 256>>>();
    moe_ffn_kernel<<<G1_BLOCKS + G2_BLOCKS, 256, SMEM_BYTES>>>(out);
}

// round 15
// speedup vs baseline: 1.2292x; 1.2292x over previous
#include <cuda_runtime.h>
#include <cuda_fp16.h>
#include <math.h>
#include <stdint.h>

// ---------------- problem constants ----------------
#define TT     16384            // tokens = B*S
#define DD     1024             // n_embd
#define EE     8                // experts
#define DFF    2048             // per-expert ffn width
#define NN     32768            // N = T*K
#define RBLOCKS 512
#define MAX_TILES 264
#define MAX_ROWS (MAX_TILES*128)
#define OUT_OFF ((size_t)TT*DD)
#define G1_BLOCKS (16*MAX_TILES)   // 4224
#define G2_BLOCKS (8*MAX_TILES)    // 2112

#define STAGES 4
#define STAGE_BYTES 16384       // A 8K | B 8K (128 rows x 64B each)
#define SMEM_BYTES (STAGES*STAGE_BYTES)

// ---------------- device scratch (~228 MiB) ----------------
__device__ int   g_counts[EE];
__device__ int   g_cursor[EE];
__device__ int   g_offpad[EE];
__device__ int   g_tile_expert[MAX_TILES];
__device__ int   g_done[MAX_TILES];
__device__ int   g_sel[NN];
__device__ float g_rw[NN];
__device__ int   g_list[MAX_ROWS];
__device__ float g_partials[RBLOCKS][17];   // z | p[8] | cnt[8]

__device__ __half g_zeroh[DD];                        // stays zero (never written)
__device__ __half g_xh[(size_t)TT*DD];                // 32 MiB (written by router)
__device__ __half g_w1t[(size_t)EE*DFF*DD];           // 32 MiB  [e*DFF+f][d]
__device__ __half g_w2t[(size_t)EE*DD*DFF];           // 32 MiB  [e*DD+d][f]
__device__ __half g_H[(size_t)MAX_ROWS*DFF];          // 132 MiB post-gelu hidden fp16

// ---------------- asm helpers (baseline sm_80+ ISA only) ----------------
__device__ __forceinline__ uint32_t smem_u32(const void* p) {
    uint32_t r;
    asm("{ .reg .u64 t; cvta.to.shared.u64 t, %1; cvt.u32.u64 %0, t; }" : "=r"(r) : "l"(p));
    return r;
}
__device__ __forceinline__ void cp16(uint32_t dst, const void* src) {
    asm volatile("cp.async.cg.shared.global [%0], [%1], 16;" :: "r"(dst), "l"(src) : "memory");
}
#define CP_COMMIT() asm volatile("cp.async.commit_group;" ::: "memory")
#define CP_WAIT0()  asm volatile("cp.async.wait_group 0;" ::: "memory")
#define CP_WAIT1()  asm volatile("cp.async.wait_group 1;" ::: "memory")
#define CP_WAIT2()  asm volatile("cp.async.wait_group 2;" ::: "memory")
#define CP_WAIT3()  asm volatile("cp.async.wait_group 3;" ::: "memory")

__device__ __forceinline__ void ldsm4(uint32_t* r, uint32_t addr) {
    asm volatile("ldmatrix.sync.aligned.m8n8.x4.shared.b16 {%0,%1,%2,%3}, [%4];"
        : "=r"(r[0]), "=r"(r[1]), "=r"(r[2]), "=r"(r[3]) : "r"(addr));
}
__device__ __forceinline__ void mma16816(float* d, const uint32_t* a, const uint32_t* b) {
    asm volatile(
        "mma.sync.aligned.m16n8k16.row.col.f32.f16.f16.f32 "
        "{%0,%1,%2,%3}, {%4,%5,%6,%7}, {%8,%9}, {%0,%1,%2,%3};"
        : "+f"(d[0]), "+f"(d[1]), "+f"(d[2]), "+f"(d[3])
        : "r"(a[0]), "r"(a[1]), "r"(a[2]), "r"(a[3]), "r"(b[0]), "r"(b[1]));
}
// swizzled byte offset inside one 128x32-fp16 smem tile (row stride 64B)
__device__ __forceinline__ uint32_t swz(int row, int c) {
    return (uint32_t)(row * 64 + ((c ^ ((row >> 1) & 3)) * 16));
}

// w1 [D][E*DFF] -> w1t [E*DFF][D] fp16 (lightweight, high occupancy)
__global__ __launch_bounds__(256) void conv_w1_kernel(const float* __restrict__ w1) {
    __shared__ float t[32][33];
    int c0 = blockIdx.x * 32, d0 = blockIdx.y * 32;
    int tx = threadIdx.x, ty = threadIdx.y;           // 32 x 8
    #pragma unroll
    for (int j = 0; j < 32; j += 8)
        t[ty + j][tx] = w1[(size_t)(d0 + ty + j) * (EE * DFF) + c0 + tx];
    __syncthreads();
    #pragma unroll
    for (int j = 0; j < 32; j += 8)
        g_w1t[(size_t)(c0 + ty + j) * DD + d0 + tx] = __float2half_rn(t[tx][ty + j]);
}

// w2 [E*DFF][D] -> w2t [e][d][f] fp16
__global__ __launch_bounds__(256) void conv_w2_kernel(const float* __restrict__ w2) {
    __shared__ float t[32][33];
    int d0 = blockIdx.x * 32, f0 = blockIdx.y * 32, e = blockIdx.z;
    int tx = threadIdx.x, ty = threadIdx.y;
    #pragma unroll
    for (int j = 0; j < 32; j += 8)
        t[ty + j][tx] = w2[(size_t)(e * DFF + f0 + ty + j) * DD + d0 + tx];
    __syncthreads();
    #pragma unroll
    for (int j = 0; j < 32; j += 8)
        g_w2t[(size_t)(e * DD + d0 + ty + j) * DFF + f0 + tx] = __float2half_rn(t[tx][ty + j]);
}

// ---------------- router: fused x->fp16, d_out zeroing, fp32 count partials --------
__global__ __launch_bounds__(256) void moe_router_kernel(
    const float* __restrict__ x, const float* __restrict__ router_w,
    float* __restrict__ d_out)
{
    __shared__ float rw_s[EE * DD];
    __shared__ float warp_part[8][17];
    // zero this block's chunk of d_out (TT*DD/4 float4s over RBLOCKS blocks)
    {
        float4* o4 = (float4*)d_out;
        int per = TT * DD / 4 / RBLOCKS;        // 8192 float4 per block
        int base = blockIdx.x * per;
        for (int i = threadIdx.x; i < per; i += 256)
            o4[base + i] = make_float4(0.f, 0.f, 0.f, 0.f);
    }
    for (int i = threadIdx.x; i < EE * DD; i += 256) rw_s[i] = router_w[i];
    __syncthreads();

    int warp = threadIdx.x >> 5, lane = threadIdx.x & 31;
    int wg = blockIdx.x * 8 + warp;
    float zp = 0.f;
    float pp[EE], cnt[EE];
    #pragma unroll
    for (int e = 0; e < EE; e++) { pp[e] = 0.f; cnt[e] = 0.f; }

    for (int t = wg; t < TT; t += RBLOCKS * 8) {
        const float* xr = x + (size_t)t * DD;
        float xv[32];
        #pragma unroll
        for (int i = 0; i < 32; i++) xv[i] = xr[lane + 32 * i];
        __half* xo = g_xh + (size_t)t * DD + lane;
        #pragma unroll
        for (int i = 0; i < 32; i++) xo[32 * i] = __float2half_rn(xv[i]);

        float logit[EE];
        #pragma unroll
        for (int e = 0; e < EE; e++) {
            float s = 0.f;
            #pragma unroll
            for (int i = 0; i < 32; i++) s = fmaf(xv[i], rw_s[e * DD + lane + 32 * i], s);
            #pragma unroll
            for (int o = 16; o > 0; o >>= 1) s += __shfl_xor_sync(0xFFFFFFFFu, s, o);
            logit[e] = s;
        }
        if (lane == 0) {
            float m = logit[0];
            #pragma unroll
            for (int e = 1; e < EE; e++) m = fmaxf(m, logit[e]);
            float se = 0.f, p[EE];
            #pragma unroll
            for (int e = 0; e < EE; e++) { p[e] = expf(logit[e] - m); se += p[e]; }
            float inv = 1.f / se;
            float lse = m + logf(se);
            zp += lse * lse;
            int i1 = -1, i2 = -1; float p1 = -1.f, p2 = -1.f;
            #pragma unroll
            for (int e = 0; e < EE; e++) {
                float pe = p[e] * inv;
                pp[e] += pe;
                if (pe > p1)      { p2 = p1; i2 = i1; p1 = pe; i1 = e; }
                else if (pe > p2) { p2 = pe; i2 = e; }
            }
            float s12 = p1 + p2;
            g_sel[2 * t] = i1;  g_sel[2 * t + 1] = i2;
            g_rw[2 * t] = p1 / s12;  g_rw[2 * t + 1] = p2 / s12;
            cnt[i1] += 1.f;
            cnt[i2] += 1.f;
        }
    }
    if (lane == 0) {
        warp_part[warp][0] = zp;
        #pragma unroll
        for (int e = 0; e < EE; e++) {
            warp_part[warp][e + 1] = pp[e];
            warp_part[warp][e + 9] = cnt[e];
        }
    }
    __syncthreads();
    if (threadIdx.x == 0) {
        float acc[17];
        #pragma unroll
        for (int j = 0; j < 17; j++) acc[j] = 0.f;
        for (int w = 0; w < 8; w++)
            for (int j = 0; j < 17; j++) acc[j] += warp_part[w][j];
        for (int j = 0; j < 17; j++) g_partials[blockIdx.x][j] = acc[j];
    }
}

// ---------------- finalize: reduce partials, losses, offsets, pads, g_done ----------
__global__ __launch_bounds__(256) void moe_finalize_kernel(float* __restrict__ d_out) {
    __shared__ float wsum[8][17];
    __shared__ int s_off[EE], s_cnt[EE], s_blk[EE];
    int tid = threadIdx.x, lane = tid & 31, warp = tid >> 5;
    float acc[17];
    #pragma unroll
    for (int j = 0; j < 17; j++) acc[j] = 0.f;
    for (int b = tid; b < RBLOCKS; b += 256)
        #pragma unroll
        for (int j = 0; j < 17; j++) acc[j] += g_partials[b][j];
    #pragma unroll
    for (int j = 0; j < 17; j++)
        #pragma unroll
        for (int o = 16; o > 0; o >>= 1) acc[j] += __shfl_xor_sync(0xFFFFFFFFu, acc[j], o);
    if (lane == 0)
        #pragma unroll
        for (int j = 0; j < 17; j++) wsum[warp][j] = acc[j];
    __syncthreads();

    if (tid == 0) {
        float tot[17];
        #pragma unroll
        for (int j = 0; j < 17; j++) {
            float s = 0.f;
            for (int w = 0; w < 8; w++) s += wsum[w][j];
            tot[j] = s;
        }
        float zl = tot[0] / (float)TT;
        float lb = 0.f, fi[EE];
        int cnts[EE];
        for (int e = 0; e < EE; e++) {
            cnts[e] = (int)lrintf(tot[e + 9]);
            fi[e] = (float)cnts[e] / (float)NN;
            lb += fi[e] * (tot[e + 1] / (float)TT);
        }
        lb *= (float)EE;
        d_out[OUT_OFF + 0] = zl;
        d_out[OUT_OFF + 1] = lb;
        for (int e = 0; e < EE; e++) d_out[OUT_OFF + 2 + e] = fi[e];

        int off = 0;
        for (int e = 0; e < EE; e++) {
            g_counts[e] = cnts[e];
            g_offpad[e] = off;
            g_cursor[e] = 0;
            int blocks = (cnts[e] + 127) >> 7;
            s_off[e] = off; s_cnt[e] = cnts[e]; s_blk[e] = blocks;
            off += blocks << 7;
        }
        int ti = 0;
        for (int e = 0; e < EE; e++)
            for (int b = 0; b < s_blk[e]; b++) g_tile_expert[ti++] = e;
        for (; ti < MAX_TILES; ti++) g_tile_expert[ti] = -1;
    }
    __syncthreads();
    // zero g_done + fill pad slots of g_list with -1 (parallel; <= 1016 pads)
    for (int i = tid; i < MAX_TILES; i += 256) g_done[i] = 0;
    for (int e = 0; e < EE; e++) {
        int start = s_off[e] + s_cnt[e];
        int end   = s_off[e] + (s_blk[e] << 7);
        for (int i = start + tid; i < end; i += 256) g_list[i] = -1;
    }
}

__global__ void moe_scatter_kernel() {
    int n = blockIdx.x * 256 + threadIdx.x;
    if (n >= NN) return;
    int e = g_sel[n];
    int pos = atomicAdd(&g_cursor[e], 1);
    g_list[g_offpad[e] + pos] = n;
}

// ================= FUSED FFN: GEMM1 blocks [0, G1_BLOCKS), GEMM2 after ==============
// GEMM2 tile (by) waits on g_done[by]==16. Deadlock-free: every GEMM2 bid > every
// GEMM1 bid, so at GEMM2 placement time all GEMM1 blocks are running or retired.
__global__ __launch_bounds__(256, 2) void moe_ffn_kernel(float* __restrict__ d_out) {
    extern __shared__ char sm[];
    __shared__ int   s_tok[128];
    __shared__ float s_rw[128];

    int bid = blockIdx.x;
    int tid = threadIdx.x;
    uint32_t sb = smem_u32(sm);
    int lane = tid & 31, w = tid >> 5;
    int wm = w >> 1, wn = w & 1;

    int rA[2], swA[2];
    #pragma unroll
    for (int mf = 0; mf < 2; mf++) {
        rA[mf] = wm * 32 + mf * 16 + (lane & 15);
        swA[mf] = (rA[mf] >> 1) & 3;
    }
    int kcA = lane >> 4;
    int rB[4], swB[4];
    #pragma unroll
    for (int np = 0; np < 4; np++) {
        rB[np] = wn * 64 + np * 16 + (lane & 7) + ((lane >> 4) << 3);
        swB[np] = (rB[np] >> 1) & 3;
    }
    int kcB = (lane >> 3) & 1;

    float acc[2][8][4];
    #pragma unroll
    for (int mf = 0; mf < 2; mf++)
        #pragma unroll
        for (int nf = 0; nf < 8; nf++)
            #pragma unroll
            for (int q = 0; q < 4; q++) acc[mf][nf][q] = 0.f;

    int arow = tid >> 1;
    int ac0 = (tid & 1) * 2;
    uint32_t d0 = swz(arow, ac0), d1 = swz(arow, ac0 + 1);
    int src0 = ac0 * 8, src1 = ac0 * 8 + 8;

    if (bid < G1_BLOCKS) {
        int bx = bid & 15, by = bid >> 4;
        int e = g_tile_expert[by];
        if (e < 0) return;

        if (tid < 128) {
            int n = g_list[by * 128 + tid];
            s_tok[tid] = (n >= 0) ? (n >> 1) : -1;
        }
        __syncthreads();

        int tok = s_tok[arow];
        const __half* Ah = (tok >= 0) ? g_xh + (size_t)tok * DD : g_zeroh;
        const __half* Bh = g_w1t + (size_t)(e * DFF + bx * 128 + arow) * DD;

        const int S = DD / 32;   // 32 slabs
        #define G1_LOAD(s) do {                                             \
            uint32_t base = sb + ((s) % STAGES) * STAGE_BYTES;              \
            int k0 = (s) * 32;                                              \
            cp16(base +    0 + d0, Ah + k0 + src0);                         \
            cp16(base +    0 + d1, Ah + k0 + src1);                         \
            cp16(base + 8192 + d0, Bh + k0 + src0);                         \
            cp16(base + 8192 + d1, Bh + k0 + src1);                         \
            CP_COMMIT();                                                    \
        } while (0)

        G1_LOAD(0); G1_LOAD(1); G1_LOAD(2);
        for (int s = 0; s < S; ++s) {
            if (s + 3 < S) { G1_LOAD(s + 3); CP_WAIT3(); }
            else if (s + 2 < S) { CP_WAIT2(); }
            else if (s + 1 < S) { CP_WAIT1(); }
            else { CP_WAIT0(); }
            __syncthreads();
            uint32_t base = sb + (s % STAGES) * STAGE_BYTES;
            #pragma unroll
            for (int kk = 0; kk < 2; ++kk) {
                uint32_t ah[2][4], bfr[4][4];
                #pragma unroll
                for (int mf = 0; mf < 2; mf++) {
                    uint32_t ao = (uint32_t)(rA[mf] * 64 + (((kk * 2 + kcA) ^ swA[mf]) * 16));
                    ldsm4(ah[mf], base + ao);
                }
                #pragma unroll
                for (int np = 0; np < 4; np++) {
                    uint32_t bo = (uint32_t)(rB[np] * 64 + (((kk * 2 + kcB) ^ swB[np]) * 16));
                    ldsm4(bfr[np], base + 8192 + bo);
                }
                #pragma unroll
                for (int mf = 0; mf < 2; mf++)
                    #pragma unroll
                    for (int np = 0; np < 4; np++) {
                        mma16816(acc[mf][np*2],   ah[mf], &bfr[np][0]);
                        mma16816(acc[mf][np*2+1], ah[mf], &bfr[np][2]);
                    }
            }
            __syncthreads();
        }
        #undef G1_LOAD

        #pragma unroll
        for (int mf = 0; mf < 2; mf++) {
            int r0 = wm * 32 + mf * 16 + (lane >> 2);
            #pragma unroll
            for (int nf = 0; nf < 8; nf++) {
                int c = wn * 64 + nf * 8 + (lane & 3) * 2;
                size_t base0 = (size_t)(by * 128 + r0) * DFF + bx * 128 + c;
                size_t base1 = (size_t)(by * 128 + r0 + 8) * DFF + bx * 128 + c;
                #pragma unroll
                for (int half_ = 0; half_ < 2; half_++) {
                    float v0 = acc[mf][nf][half_ * 2], v1 = acc[mf][nf][half_ * 2 + 1];
                    float gl0 = 0.5f * v0 * (1.f + erff(v0 * 0.70710678118654752f));
                    float gl1 = 0.5f * v1 * (1.f + erff(v1 * 0.70710678118654752f));
                    *(__half2*)(g_H + (half_ ? base1 : base0)) = __floats2half2_rn(gl0, gl1);
                }
            }
        }
        __threadfence();
        __syncthreads();
        if (tid == 0) atomicAdd(&g_done[by], 1);
    } else {
        int n2 = bid - G1_BLOCKS;
        int bx = n2 & 7, by = n2 >> 3;
        int e = g_tile_expert[by];
        if (e < 0) return;

        if (tid < 128) {
            int n = g_list[by * 128 + tid];
            s_tok[tid] = n;
            s_rw[tid] = (n >= 0) ? g_rw[n] : 0.f;
        }
        if (tid == 0) {
            int v;
            do {
                asm volatile("ld.global.acquire.gpu.b32 %0, [%1];"
                             : "=r"(v) : "l"(&g_done[by]) : "memory");
            } while (v < 16);
        }
        __syncthreads();

        const __half* Ah = g_H + (size_t)(by * 128 + arow) * DFF;
        const __half* Bh = g_w2t + (size_t)(e * DD + bx * 128 + arow) * DFF;

        const int S = DFF / 32;   // 64 slabs
        #define G2_LOAD(s) do {                                             \
            uint32_t base = sb + ((s) % STAGES) * STAGE_BYTES;              \
            int k0 = (s) * 32;                                              \
            cp16(base +    0 + d0, Ah + k0 + src0);                         \
            cp16(base +    0 + d1, Ah + k0 + src1);                         \
            cp16(base + 8192 + d0, Bh + k0 + src0);                         \
            cp16(base + 8192 + d1, Bh + k0 + src1);                         \
            CP_COMMIT();                                                    \
        } while (0)

        G2_LOAD(0); G2_LOAD(1); G2_LOAD(2);
        for (int s = 0; s < S; ++s) {
            if (s + 3 < S) { G2_LOAD(s + 3); CP_WAIT3(); }
            else if (s + 2 < S) { CP_WAIT2(); }
            else if (s + 1 < S) { CP_WAIT1(); }
            else { CP_WAIT0(); }
            __syncthreads();
            uint32_t base = sb + (s % STAGES) * STAGE_BYTES;
            #pragma unroll
            for (int kk = 0; kk < 2; ++kk) {
                uint32_t ah[2][4], bfr[4][4];
                #pragma unroll
                for (int mf = 0; mf < 2; mf++) {
                    uint32_t ao = (uint32_t)(rA[mf] * 64 + (((kk * 2 + kcA) ^ swA[mf]) * 16));
                    ldsm4(ah[mf], base + ao);
                }
                #pragma unroll
                for (int np = 0; np < 4; np++) {
                    uint32_t bo = (uint32_t)(rB[np] * 64 + (((kk * 2 + kcB) ^ swB[np]) * 16));
                    ldsm4(bfr[np], base + 8192 + bo);
                }
                #pragma unroll
                for (int mf = 0; mf < 2; mf++)
                    #pragma unroll
                    for (int np = 0; np < 4; np++) {
                        mma16816(acc[mf][np*2],   ah[mf], &bfr[np][0]);
                        mma16816(acc[mf][np*2+1], ah[mf], &bfr[np][2]);
                    }
            }
            __syncthreads();
        }
        #undef G2_LOAD

        #pragma unroll
        for (int mf = 0; mf < 2; mf++) {
            int r0 = wm * 32 + mf * 16 + (lane >> 2);
            int n0 = s_tok[r0], n1 = s_tok[r0 + 8];
            float w0 = s_rw[r0], w1v = s_rw[r0 + 8];
            #pragma unroll
            for (int nf = 0; nf < 8; nf++) {
                int c = bx * 128 + wn * 64 + nf * 8 + (lane & 3) * 2;
                if (n0 >= 0) {
                    float* p = d_out + (size_t)(n0 >> 1) * DD + c;
                    atomicAdd(p,     acc[mf][nf][0] * w0);
                    atomicAdd(p + 1, acc[mf][nf][1] * w0);
                }
                if (n1 >= 0) {
                    float* p = d_out + (size_t)(n1 >> 1) * DD + c;
                    atomicAdd(p,     acc[mf][nf][2] * w1v);
                    atomicAdd(p + 1, acc[mf][nf][3] * w1v);
                }
            }
        }
    }
}

// ---------------- launch ----------------
extern "C" void kernel_launch(void* const* d_in, const int* in_sizes, int n_in,
                              void* d_out, int out_size) {
    const float* x        = (const float*)d_in[0];
    const float* w1       = (const float*)d_in[1];
    const float* w2       = (const float*)d_in[2];
    const float* router_w = (const float*)d_in[3];
    float* out = (float*)d_out;

    cudaFuncSetAttribute(moe_ffn_kernel, cudaFuncAttributeMaxDynamicSharedMemorySize, SMEM_BYTES);

    conv_w1_kernel<<<dim3(EE * DFF / 32, DD / 32), dim3(32, 8)>>>(w1);
    conv_w2_kernel<<<dim3(DD / 32, DFF / 32, EE), dim3(32, 8)>>>(w2);
    moe_router_kernel<<<RBLOCKS, 256>>>(x, router_w, out);
    moe_finalize_kernel<<<1, 256>>>(out);
    moe_scatter_kernel<<<(NN + 255) / 256, 256>>>();
    moe_ffn_kernel<<<G1_BLOCKS + G2_BLOCKS, 256, SMEM_BYTES>>>(out);
}